// round 16
// baseline (speedup 1.0000x reference)
#include <cuda_runtime.h>
#include <cuda_bf16.h>
#include <cstdint>

#define NS 512
#define NV 32000
#define NB 16
#define NT 128

// ---- scratch (no cudaMalloc allowed) ----
__device__ float g_lse_em[NS];
__device__ float g_pi[NS];
__device__ float g_PT[NS * NS];          // PT[c][s] = softmax(tm)[s][c]
__device__ float g_E[NB * NT * NS];      // E[b][t][s] = exp(log_em[s, x_bt])
__device__ float g_L[NB];                // per-batch log-likelihood
__device__ unsigned g_done;              // completion counter for in-kernel final

// ---- helpers ----
__device__ __forceinline__ unsigned smem_u32(const void* p) {
    return (unsigned)__cvta_generic_to_shared(p);
}
__device__ __forceinline__ unsigned mapa_u32(unsigned local, unsigned rank) {
    unsigned r;
    asm("mapa.shared::cluster.u32 %0, %1, %2;" : "=r"(r) : "r"(local), "r"(rank));
    return r;
}
#define MBAR_INIT(mb, cnt) \
    asm volatile("mbarrier.init.shared.b64 [%0], %1;" :: "r"(mb), "r"(cnt) : "memory")
#define MBAR_EXPECT_TX(mb, bytes) \
    asm volatile("mbarrier.arrive.expect_tx.shared.b64 _, [%0], %1;" :: "r"(mb), "r"(bytes) : "memory")
// HW-sleep wait (suspend hint keeps spinners off the SMEM port)
#define MBAR_WAIT_CLUSTER(mb, parity) do {                                                       \
    asm volatile("{\n\t.reg .pred P;\n\tW%=:\n\t"                                                \
        "mbarrier.try_wait.parity.acquire.cluster.shared::cta.b64 P, [%0], %1, 0x989680;\n\t"    \
        "@!P bra W%=;\n\t}" :: "r"(mb), "r"(parity) : "memory");                                 \
} while (0)
// 8-byte DSMEM push (2x bf16x2 = 4 columns) with tx accounting
__device__ __forceinline__ void st_async_b64(unsigned raddr, unsigned long long v, unsigned rmbar) {
    asm volatile(
        "st.async.shared::cluster.mbarrier::complete_tx::bytes.b64 [%0], %1, [%2];"
        :: "r"(raddr), "l"(v), "r"(rmbar) : "memory");
}
// packed f32x2 math
#define FMA2(d, a, b, c) \
    asm("fma.rn.f32x2 %0, %1, %2, %3;" : "=l"(d) : "l"(a), "l"(b), "l"(c))
#define ADD2(d, a, b) \
    asm("add.rn.f32x2 %0, %1, %2;" : "=l"(d) : "l"(a), "l"(b))
__device__ __forceinline__ float hadd2(unsigned long long v) {
    float lo, hi;
    asm("mov.b64 {%0, %1}, %2;" : "=f"(lo), "=f"(hi) : "l"(v));
    return lo + hi;
}
// pack two u32 (f32 bit patterns) into a f32x2 64-bit operand
__device__ __forceinline__ unsigned long long pack64(unsigned lo, unsigned hi) {
    unsigned long long r;
    asm("mov.b64 %0, {%1, %2};" : "=l"(r) : "r"(lo), "r"(hi));
    return r;
}
// pack two f32 into bf16x2 (lo, hi)
#define PACK_BF16X2(r, lo, hi) \
    asm("cvt.rn.bf16x2.f32 %0, %1, %2;" : "=r"(r) : "f"(hi), "f"(lo))

// ===================== K1: row logsumexp of em [512, 32000] =====================
__global__ void k_lse_em(const float* __restrict__ em) {
    const int row = blockIdx.x;
    const float4* r = (const float4*)(em + (size_t)row * NV);
    const int n4 = NV / 4;  // 8000

    __shared__ float sm[8];

    float m = -1e30f;
    for (int i = threadIdx.x; i < n4; i += blockDim.x) {
        float4 x = r[i];
        m = fmaxf(m, fmaxf(fmaxf(x.x, x.y), fmaxf(x.z, x.w)));
    }
    #pragma unroll
    for (int o = 16; o; o >>= 1) m = fmaxf(m, __shfl_xor_sync(~0u, m, o));
    if ((threadIdx.x & 31) == 0) sm[threadIdx.x >> 5] = m;
    __syncthreads();
    if (threadIdx.x < 32) {
        float mm = (threadIdx.x < (blockDim.x >> 5)) ? sm[threadIdx.x] : -1e30f;
        #pragma unroll
        for (int o = 4; o; o >>= 1) mm = fmaxf(mm, __shfl_xor_sync(~0u, mm, o));
        if (threadIdx.x == 0) sm[0] = mm;
    }
    __syncthreads();
    m = sm[0];
    __syncthreads();

    float s = 0.f;
    for (int i = threadIdx.x; i < n4; i += blockDim.x) {
        float4 x = r[i];
        s += __expf(x.x - m) + __expf(x.y - m) + __expf(x.z - m) + __expf(x.w - m);
    }
    #pragma unroll
    for (int o = 16; o; o >>= 1) s += __shfl_xor_sync(~0u, s, o);
    if ((threadIdx.x & 31) == 0) sm[threadIdx.x >> 5] = s;
    __syncthreads();
    if (threadIdx.x == 0) {
        float tot = 0.f;
        for (int wi = 0; wi < (blockDim.x >> 5); wi++) tot += sm[wi];
        g_lse_em[row] = m + __logf(tot);
    }
}

// ===================== K2: P^T = softmax(tm) transposed; pi = softmax(p) ========
__global__ void k_tm_pi(const float* __restrict__ tm, const float* __restrict__ p) {
    __shared__ float sm[4];
    __shared__ float red;
    const int tid = threadIdx.x;  // 128 threads

    // reset the completion counter for this launch (stream-ordered before k_forward)
    if (blockIdx.x == NS && tid == 0) g_done = 0;

    const float* src = (blockIdx.x < NS) ? (tm + (size_t)blockIdx.x * NS) : p;

    float m = -1e30f;
    #pragma unroll
    for (int k = 0; k < 4; k++) m = fmaxf(m, src[tid + 128 * k]);
    #pragma unroll
    for (int o = 16; o; o >>= 1) m = fmaxf(m, __shfl_xor_sync(~0u, m, o));
    if ((tid & 31) == 0) sm[tid >> 5] = m;
    __syncthreads();
    if (tid == 0) red = fmaxf(fmaxf(sm[0], sm[1]), fmaxf(sm[2], sm[3]));
    __syncthreads();
    m = red;

    float s = 0.f;
    #pragma unroll
    for (int k = 0; k < 4; k++) s += __expf(src[tid + 128 * k] - m);
    #pragma unroll
    for (int o = 16; o; o >>= 1) s += __shfl_xor_sync(~0u, s, o);
    if ((tid & 31) == 0) sm[tid >> 5] = s;
    __syncthreads();
    if (tid == 0) red = m + __logf(sm[0] + sm[1] + sm[2] + sm[3]);
    __syncthreads();
    const float lse = red;

    if (blockIdx.x < NS) {
        const int row = blockIdx.x;  // source state s
        #pragma unroll
        for (int k = 0; k < 4; k++) {
            int c = tid + 128 * k;   // dest state
            g_PT[(size_t)c * NS + row] = __expf(src[c] - lse);
        }
    } else {
        #pragma unroll
        for (int k = 0; k < 4; k++) {
            int i = tid + 128 * k;
            g_pi[i] = __expf(p[i] - lse);
        }
    }
}

// ===================== K3: gather E[b][t][s] = exp(em[s, id] - lse_em[s]) =======
__global__ void k_gather(const float* __restrict__ em, const int* __restrict__ ids) {
    const int bt = blockIdx.x;           // 0..2047
    int id = ids[bt];
    id = (id < 0) ? 0 : ((id >= NV) ? NV - 1 : id);
    const float* col = em + id;
    #pragma unroll
    for (int k = 0; k < 4; k++) {
        int s = threadIdx.x + 128 * k;   // blockDim = 128
        g_E[(size_t)bt * NS + s] = __expf(col[(size_t)s * NV] - g_lse_em[s]);
    }
}

// ===================== K4: clustered scaled-forward recurrence ==================
// R15 core + ONE change: the exchanged vector is bf16 (payload halved, 1024 B
// per step per CTA instead of 2048). Tests the per-byte DSMEM tx-processing
// floor theory. Receiver expands bf16->f32 with pure ALU (<<16 / &0xFFFF0000);
// sender packs with cvt.rn.bf16x2.f32 and pushes ONE st.async.b64 per peer.
__global__ void __cluster_dims__(8, 1, 1) __launch_bounds__(512, 1)
k_forward(float* __restrict__ out) {
    __shared__ __align__(16) unsigned buf32[2][NS / 2];   // bf16 pairs
    __shared__ __align__(8) unsigned long long mbars[2];

    const int tid = threadIdx.x;
    const int w = tid >> 5;
    const int l = tid & 31;
    unsigned rank;
    asm("mov.u32 %0, %%cluster_ctarank;" : "=r"(rank));
    const int g = blockIdx.x >> 3;                 // batch / cluster id
    const int colbase = (int)rank * 64 + w * 4;    // this warp's 4 columns

    // --- P^T chunk into packed registers ---
    unsigned long long Pa[4][4], Pb[4][4];
    #pragma unroll
    for (int j = 0; j < 4; j++)
        #pragma unroll
        for (int k = 0; k < 4; k++) {
            ulonglong2 pp = *(const ulonglong2*)&g_PT[(size_t)(colbase + j) * NS + 4 * l + 128 * k];
            Pa[j][k] = pp.x;
            Pb[j][k] = pp.y;
        }

    const unsigned mb0 = smem_u32(&mbars[0]);
    const unsigned mb1 = smem_u32(&mbars[1]);
    if (tid == 0) { MBAR_INIT(mb0, 1); MBAR_INIT(mb1, 1); }

    const float* Eb = g_E + (size_t)g * NT * NS;

    // --- t = 0: every CTA computes the full v0 = pi * E0 locally (bf16) ---
    ((__nv_bfloat16*)&buf32[0][0])[tid] = __float2bfloat16(g_pi[tid] * Eb[tid]);
    __syncthreads();
    // peers' mbarriers must be initialized before any st.async targets them
    asm volatile("barrier.cluster.arrive.aligned;" ::: "memory");
    asm volatile("barrier.cluster.wait.aligned;"   ::: "memory");

    // --- per-lane remote addresses (lanes 0..7 push to peer = lane index) ---
    unsigned rbuf = 0, rmb0 = 0, rmb1 = 0;
    if (l < 8) {
        rbuf = mapa_u32(smem_u32(&buf32[0][0]), (unsigned)l);
        rmb0 = mapa_u32(mb0, (unsigned)l);
        rmb1 = mapa_u32(mb1, (unsigned)l);
    }

    int ph0 = 0, ph1 = 0;
    float L = 0.f;
    float4 e4 = *(const float4*)&Eb[1 * NS + colbase];   // emission for t=1

    for (int t = 1; t < NT; t++) {
        const int sp = (t - 1) & 1;   // slot holding v_{t-1}
        const int sc = t & 1;         // slot receiving v_t

        // wait for v_{t-1}: ONLY warp 0 polls the mbarrier; bar.sync releases
        if (t >= 2) {
            if (w == 0) {
                if (sp) MBAR_WAIT_CLUSTER(mb1, ph1);
                else    MBAR_WAIT_CLUSTER(mb0, ph0);
            }
            __syncthreads();
        }
        // arm this step's receive barrier (1024 B = 8 ranks x 16 warps x 8 B)
        if (tid == 0) MBAR_EXPECT_TX(sc ? mb1 : mb0, 1024u);

        // prefetch NEXT step's emission factors (off critical path)
        const int tn = (t + 1 < NT) ? t + 1 : t;
        const float4 e4n = *(const float4*)&Eb[tn * NS + colbase];

        // packed dot over the 512-vector (bf16 -> f32 expand via ALU) + S_prev sum
        const unsigned* cur = buf32[sp];
        unsigned long long acc0 = 0, acc1 = 0, acc2 = 0, acc3 = 0, ssp = 0;
        #pragma unroll
        for (int k = 0; k < 4; k++) {
            uint2 cc = *(const uint2*)&cur[2 * l + 64 * k];  // 4 bf16 sources
            const unsigned long long ax = pack64(cc.x << 16, cc.x & 0xFFFF0000u);
            const unsigned long long ay = pack64(cc.y << 16, cc.y & 0xFFFF0000u);
            FMA2(acc0, ax, Pa[0][k], acc0); FMA2(acc0, ay, Pb[0][k], acc0);
            FMA2(acc1, ax, Pa[1][k], acc1); FMA2(acc1, ay, Pb[1][k], acc1);
            FMA2(acc2, ax, Pa[2][k], acc2); FMA2(acc2, ay, Pb[2][k], acc2);
            FMA2(acc3, ax, Pa[3][k], acc3); FMA2(acc3, ay, Pb[3][k], acc3);
            ADD2(ssp, ssp, ax); ADD2(ssp, ssp, ay);
        }
        float a0 = hadd2(acc0), a1 = hadd2(acc1), a2 = hadd2(acc2), a3 = hadd2(acc3);
        float ss = hadd2(ssp);

        // reduce-scatter butterfly: octet o (= l>>3) ends holding full acc_o
        float p0 = (l & 16) ? a2 : a0;
        float q0 = (l & 16) ? a0 : a2;
        float p1 = (l & 16) ? a3 : a1;
        float q1 = (l & 16) ? a1 : a3;
        p0 += __shfl_xor_sync(~0u, q0, 16);
        p1 += __shfl_xor_sync(~0u, q1, 16);
        float pp = (l & 8) ? p1 : p0;
        float qq = (l & 8) ? p0 : p1;
        pp += __shfl_xor_sync(~0u, qq, 8);
        pp += __shfl_xor_sync(~0u, pp, 4);
        pp += __shfl_xor_sync(~0u, pp, 2);
        pp += __shfl_xor_sync(~0u, pp, 1);
        // regather: every lane builds (a0,a1,a2,a3) from octet representatives
        const int lb = l & 7;
        const float v0 = __shfl_sync(~0u, pp, lb);
        const float v1 = __shfl_sync(~0u, pp, 8 + lb);
        const float v2 = __shfl_sync(~0u, pp, 16 + lb);
        const float v3 = __shfl_sync(~0u, pp, 24 + lb);
        // full butterfly for ss (S_{t-1}; every lane needs it)
        #pragma unroll
        for (int o = 16; o; o >>= 1) ss += __shfl_xor_sync(~0u, ss, o);
        const float invS = __fdividef(1.f, ss);

        // push this warp's 4 scaled columns (bf16) to all 8 CTAs (lane r -> peer r)
        if (l < 8) {
            unsigned w0, w1;
            PACK_BF16X2(w0, v0 * invS * e4.x, v1 * invS * e4.y);
            PACK_BF16X2(w1, v2 * invS * e4.z, v3 * invS * e4.w);
            const unsigned daddr = rbuf + (unsigned)((sc * (NS / 2) + (colbase >> 1)) * 4);
            st_async_b64(daddr, pack64(w0, w1), sc ? rmb1 : rmb0);
        }
        if (rank == 0 && tid == 0) L += __logf(ss);
        e4 = e4n;
        if (t >= 2) { if (sp) ph1 ^= 1; else ph0 ^= 1; }
    }

    // --- final S_{T-1} term: v_127 lives in slot 1 / mbar 1 ---
    if (w == 0) MBAR_WAIT_CLUSTER(mb1, ph1);
    __syncthreads();
    {
        const unsigned* cur = buf32[1];
        unsigned long long ssp = 0;
        #pragma unroll
        for (int k = 0; k < 4; k++) {
            uint2 cc = *(const uint2*)&cur[2 * l + 64 * k];
            ADD2(ssp, ssp, pack64(cc.x << 16, cc.x & 0xFFFF0000u));
            ADD2(ssp, ssp, pack64(cc.y << 16, cc.y & 0xFFFF0000u));
        }
        float ss = hadd2(ssp);
        #pragma unroll
        for (int o = 16; o; o >>= 1) ss += __shfl_xor_sync(~0u, ss, o);
        if (rank == 0 && tid == 0) {
            L += __logf(ss);
            g_L[g] = L;
            __threadfence();                     // publish g_L[g]
            unsigned old = atomicAdd(&g_done, 1u);
            if (old == NB - 1) {                 // last cluster: final reduce
                __threadfence();                 // acquire all g_L[]
                float s = 0.f;
                #pragma unroll
                for (int i = 0; i < NB; i++) s += g_L[i];
                out[0] = -s / (float)NB;
            }
        }
    }
    // align exits: no CTA leaves while a peer could still target its smem
    asm volatile("barrier.cluster.arrive.aligned;" ::: "memory");
    asm volatile("barrier.cluster.wait.aligned;"   ::: "memory");
}

// ===================== launch ====================================================
extern "C" void kernel_launch(void* const* d_in, const int* in_sizes, int n_in,
                              void* d_out, int out_size) {
    const float* em = nullptr;
    const float* tm = nullptr;
    const float* p  = nullptr;
    const int* ids  = nullptr;
    for (int i = 0; i < n_in; i++) {
        if (in_sizes[i] == NB * NT)      ids = (const int*)d_in[i];
        else if (in_sizes[i] == NS * NV) em  = (const float*)d_in[i];
        else if (in_sizes[i] == NS * NS) tm  = (const float*)d_in[i];
        else if (in_sizes[i] == NS)      p   = (const float*)d_in[i];
    }

    k_lse_em<<<NS, 256>>>(em);
    k_tm_pi<<<NS + 1, 128>>>(tm, p);
    k_gather<<<NB * NT, 128>>>(em, ids);

    {
        cudaLaunchConfig_t cfg = {};
        cfg.gridDim  = dim3(NB * 8, 1, 1);
        cfg.blockDim = dim3(512, 1, 1);
        cfg.dynamicSmemBytes = 0;
        cfg.stream = 0;
        cudaLaunchAttribute attrs[1];
        attrs[0].id = cudaLaunchAttributeClusterDimension;
        attrs[0].val.clusterDim.x = 8;
        attrs[0].val.clusterDim.y = 1;
        attrs[0].val.clusterDim.z = 1;
        cfg.attrs = attrs;
        cfg.numAttrs = 1;
        cudaLaunchKernelEx(&cfg, k_forward, (float*)d_out);
    }
}

// round 17
// speedup vs baseline: 1.0459x; 1.0459x over previous
#include <cuda_runtime.h>
#include <cstdint>

#define NS 512
#define NV 32000
#define NB 16
#define NT 128

// ---- scratch (no cudaMalloc allowed) ----
__device__ float g_lse_em[NS];
__device__ float g_pm[2048];             // per-chunk max partials
__device__ float g_ps[2048];             // per-chunk sum partials
__device__ float g_pi[NS];
__device__ float g_PT[NS * NS];          // PT[c][s] = softmax(tm)[s][c]
__device__ float g_E[NB * NT * NS];      // E[b][t][s] = exp(log_em[s, x_bt])
__device__ float g_L[NB];                // per-batch log-likelihood
__device__ unsigned g_done;              // completion counter for in-kernel final

// ---- helpers ----
__device__ __forceinline__ unsigned smem_u32(const void* p) {
    return (unsigned)__cvta_generic_to_shared(p);
}
__device__ __forceinline__ unsigned mapa_u32(unsigned local, unsigned rank) {
    unsigned r;
    asm("mapa.shared::cluster.u32 %0, %1, %2;" : "=r"(r) : "r"(local), "r"(rank));
    return r;
}
#define MBAR_INIT(mb, cnt) \
    asm volatile("mbarrier.init.shared.b64 [%0], %1;" :: "r"(mb), "r"(cnt) : "memory")
#define MBAR_EXPECT_TX(mb, bytes) \
    asm volatile("mbarrier.arrive.expect_tx.shared.b64 _, [%0], %1;" :: "r"(mb), "r"(bytes) : "memory")
// HW-sleep wait (suspend hint keeps spinners off the SMEM port)
#define MBAR_WAIT_CLUSTER(mb, parity) do {                                                       \
    asm volatile("{\n\t.reg .pred P;\n\tW%=:\n\t"                                                \
        "mbarrier.try_wait.parity.acquire.cluster.shared::cta.b64 P, [%0], %1, 0x989680;\n\t"    \
        "@!P bra W%=;\n\t}" :: "r"(mb), "r"(parity) : "memory");                                 \
} while (0)
__device__ __forceinline__ void st_async_v4(unsigned raddr, float4 v, unsigned rmbar) {
    asm volatile(
        "st.async.shared::cluster.mbarrier::complete_tx::bytes.v4.f32 "
        "[%0], {%1, %2, %3, %4}, [%5];"
        :: "r"(raddr), "f"(v.x), "f"(v.y), "f"(v.z), "f"(v.w), "r"(rmbar) : "memory");
}
// packed f32x2 math
#define FMA2(d, a, b, c) \
    asm("fma.rn.f32x2 %0, %1, %2, %3;" : "=l"(d) : "l"(a), "l"(b), "l"(c))
#define ADD2(d, a, b) \
    asm("add.rn.f32x2 %0, %1, %2;" : "=l"(d) : "l"(a), "l"(b))
__device__ __forceinline__ float hadd2(unsigned long long v) {
    float lo, hi;
    asm("mov.b64 {%0, %1}, %2;" : "=f"(lo), "=f"(hi) : "l"(v));
    return lo + hi;
}

// ===================== K1: one-pass partial LSE of em chunks ====================
// 2048 blocks = 512 rows x 4 chunks of 8000 floats. Stream the chunk from DRAM
// ONCE into SMEM (32KB), computing the running max; then sum exp from SMEM.
__global__ void k_lse_part(const float* __restrict__ em) {
    __shared__ float4 sb[2000];
    __shared__ float sm[8];
    __shared__ float red;
    const int tid = threadIdx.x;   // 256
    const int row = blockIdx.x >> 2;
    const int part = blockIdx.x & 3;
    const float4* src = (const float4*)(em + (size_t)row * NV + part * 8000);

    float m = -1e30f;
    for (int i = tid; i < 2000; i += 256) {
        float4 x = src[i];
        sb[i] = x;
        m = fmaxf(m, fmaxf(fmaxf(x.x, x.y), fmaxf(x.z, x.w)));
    }
    #pragma unroll
    for (int o = 16; o; o >>= 1) m = fmaxf(m, __shfl_xor_sync(~0u, m, o));
    if ((tid & 31) == 0) sm[tid >> 5] = m;
    __syncthreads();
    if (tid == 0) {
        float mm = sm[0];
        #pragma unroll
        for (int wi = 1; wi < 8; wi++) mm = fmaxf(mm, sm[wi]);
        red = mm;
    }
    __syncthreads();
    m = red;
    __syncthreads();

    float s = 0.f;
    for (int i = tid; i < 2000; i += 256) {
        float4 x = sb[i];
        s += __expf(x.x - m) + __expf(x.y - m) + __expf(x.z - m) + __expf(x.w - m);
    }
    #pragma unroll
    for (int o = 16; o; o >>= 1) s += __shfl_xor_sync(~0u, s, o);
    if ((tid & 31) == 0) sm[tid >> 5] = s;
    __syncthreads();
    if (tid == 0) {
        float tot = 0.f;
        #pragma unroll
        for (int wi = 0; wi < 8; wi++) tot += sm[wi];
        g_pm[blockIdx.x] = m;
        g_ps[blockIdx.x] = tot;
    }
}

// ===================== K2: softmax(tm) rows, softmax(p), LSE combine ============
// blocks [0, NS): tm rows; block NS: p (+ g_done reset); block NS+1: combine
// the 4 per-chunk LSE partials of each em row -> g_lse_em.
__global__ void k_tm_pi(const float* __restrict__ tm, const float* __restrict__ p) {
    __shared__ float sm[4];
    __shared__ float red;
    const int tid = threadIdx.x;  // 128 threads

    if (blockIdx.x == NS + 1) {
        #pragma unroll
        for (int rr = 0; rr < 4; rr++) {
            const int r = tid + 128 * rr;
            float m0 = g_pm[4 * r], m1 = g_pm[4 * r + 1];
            float m2 = g_pm[4 * r + 2], m3 = g_pm[4 * r + 3];
            float mx = fmaxf(fmaxf(m0, m1), fmaxf(m2, m3));
            float s = g_ps[4 * r] * __expf(m0 - mx) + g_ps[4 * r + 1] * __expf(m1 - mx)
                    + g_ps[4 * r + 2] * __expf(m2 - mx) + g_ps[4 * r + 3] * __expf(m3 - mx);
            g_lse_em[r] = mx + __logf(s);
        }
        return;
    }

    // reset the completion counter for this launch (stream-ordered before k_forward)
    if (blockIdx.x == NS && tid == 0) g_done = 0;

    const float* src = (blockIdx.x < NS) ? (tm + (size_t)blockIdx.x * NS) : p;

    float m = -1e30f;
    #pragma unroll
    for (int k = 0; k < 4; k++) m = fmaxf(m, src[tid + 128 * k]);
    #pragma unroll
    for (int o = 16; o; o >>= 1) m = fmaxf(m, __shfl_xor_sync(~0u, m, o));
    if ((tid & 31) == 0) sm[tid >> 5] = m;
    __syncthreads();
    if (tid == 0) red = fmaxf(fmaxf(sm[0], sm[1]), fmaxf(sm[2], sm[3]));
    __syncthreads();
    m = red;

    float s = 0.f;
    #pragma unroll
    for (int k = 0; k < 4; k++) s += __expf(src[tid + 128 * k] - m);
    #pragma unroll
    for (int o = 16; o; o >>= 1) s += __shfl_xor_sync(~0u, s, o);
    if ((tid & 31) == 0) sm[tid >> 5] = s;
    __syncthreads();
    if (tid == 0) red = m + __logf(sm[0] + sm[1] + sm[2] + sm[3]);
    __syncthreads();
    const float lse = red;

    if (blockIdx.x < NS) {
        const int row = blockIdx.x;  // source state s
        #pragma unroll
        for (int k = 0; k < 4; k++) {
            int c = tid + 128 * k;   // dest state
            g_PT[(size_t)c * NS + row] = __expf(src[c] - lse);
        }
    } else {
        #pragma unroll
        for (int k = 0; k < 4; k++) {
            int i = tid + 128 * k;
            g_pi[i] = __expf(p[i] - lse);
        }
    }
}

// ===================== K3: gather E[b][t][s] = exp(em[s, id] - lse_em[s]) =======
__global__ void k_gather(const float* __restrict__ em, const int* __restrict__ ids) {
    const int bt = blockIdx.x;           // 0..2047
    int id = ids[bt];
    id = (id < 0) ? 0 : ((id >= NV) ? NV - 1 : id);
    const float* col = em + id;
    #pragma unroll
    for (int k = 0; k < 4; k++) {
        int s = threadIdx.x + 128 * k;   // blockDim = 128
        g_E[(size_t)bt * NS + s] = __expf(col[(size_t)s * NV] - g_lse_em[s]);
    }
}

// ===================== K4: clustered scaled-forward recurrence ==================
// R12/R15 core reshaped: 256 threads / 8 warps, EACH WARP OWNS 8 COLUMNS
// (P chunk = 128 regs/thread). Same FMA per SMSP but 2 warps instead of 4:
// the tail warp (which gates every consumer's mbar completion) finishes
// earlier; LDS traffic and bar scope halve.
__global__ void __cluster_dims__(8, 1, 1) __launch_bounds__(256, 1)
k_forward(float* __restrict__ out) {
    __shared__ __align__(16) float buf[2][NS];
    __shared__ __align__(8) unsigned long long mbars[2];

    const int tid = threadIdx.x;
    const int w = tid >> 5;        // 0..7
    const int l = tid & 31;
    unsigned rank;
    asm("mov.u32 %0, %%cluster_ctarank;" : "=r"(rank));
    const int g = blockIdx.x >> 3;                 // batch / cluster id
    const int colbase = (int)rank * 64 + w * 8;    // this warp's 8 columns

    // --- P^T chunk into packed registers: 8 cols x 16 sources per lane ---
    unsigned long long Pa[8][4], Pb[8][4];
    #pragma unroll
    for (int j = 0; j < 8; j++)
        #pragma unroll
        for (int k = 0; k < 4; k++) {
            ulonglong2 pp = *(const ulonglong2*)&g_PT[(size_t)(colbase + j) * NS + 4 * l + 128 * k];
            Pa[j][k] = pp.x;
            Pb[j][k] = pp.y;
        }

    const unsigned mb0 = smem_u32(&mbars[0]);
    const unsigned mb1 = smem_u32(&mbars[1]);
    if (tid == 0) { MBAR_INIT(mb0, 1); MBAR_INIT(mb1, 1); }

    const float* Eb = g_E + (size_t)g * NT * NS;

    // --- t = 0: every CTA computes the full v0 = pi * E0 locally ---
    buf[0][tid]       = g_pi[tid]       * Eb[tid];
    buf[0][tid + 256] = g_pi[tid + 256] * Eb[tid + 256];
    __syncthreads();
    // peers' mbarriers must be initialized before any st.async targets them
    asm volatile("barrier.cluster.arrive.aligned;" ::: "memory");
    asm volatile("barrier.cluster.wait.aligned;"   ::: "memory");

    // --- per-lane remote addresses (lanes 0..7 push to peer = lane index) ---
    unsigned rbuf = 0, rmb0 = 0, rmb1 = 0;
    if (l < 8) {
        rbuf = mapa_u32(smem_u32(&buf[0][0]), (unsigned)l);
        rmb0 = mapa_u32(mb0, (unsigned)l);
        rmb1 = mapa_u32(mb1, (unsigned)l);
    }

    int ph0 = 0, ph1 = 0;
    float L = 0.f;
    float4 eA = *(const float4*)&Eb[1 * NS + colbase];       // emission t=1, cols 0-3
    float4 eB = *(const float4*)&Eb[1 * NS + colbase + 4];   // cols 4-7

    for (int t = 1; t < NT; t++) {
        const int sp = (t - 1) & 1;   // slot holding v_{t-1}
        const int sc = t & 1;         // slot receiving v_t

        // wait for v_{t-1}: ONLY warp 0 polls the mbarrier; bar.sync releases
        if (t >= 2) {
            if (w == 0) {
                if (sp) MBAR_WAIT_CLUSTER(mb1, ph1);
                else    MBAR_WAIT_CLUSTER(mb0, ph0);
            }
            __syncthreads();
        }
        // arm this step's receive barrier (2048 B = 8 ranks x 8 warps x 32 B)
        if (tid == 0) MBAR_EXPECT_TX(sc ? mb1 : mb0, 2048u);

        // prefetch NEXT step's emission factors (off critical path)
        const int tn = (t + 1 < NT) ? t + 1 : t;
        const float4 eAn = *(const float4*)&Eb[tn * NS + colbase];
        const float4 eBn = *(const float4*)&Eb[tn * NS + colbase + 4];

        // packed dot: 8 columns over the 512-vector + packed S_prev sum
        const float* cur = buf[sp];
        unsigned long long acc[8] = {0, 0, 0, 0, 0, 0, 0, 0};
        unsigned long long ssp = 0;
        #pragma unroll
        for (int k = 0; k < 4; k++) {
            ulonglong2 aa = *(const ulonglong2*)&cur[4 * l + 128 * k];
            #pragma unroll
            for (int j = 0; j < 8; j++) {
                FMA2(acc[j], aa.x, Pa[j][k], acc[j]);
                FMA2(acc[j], aa.y, Pb[j][k], acc[j]);
            }
            ADD2(ssp, ssp, aa.x); ADD2(ssp, ssp, aa.y);
        }
        float a0 = hadd2(acc[0]), a1 = hadd2(acc[1]), a2 = hadd2(acc[2]), a3 = hadd2(acc[3]);
        float a4 = hadd2(acc[4]), a5 = hadd2(acc[5]), a6 = hadd2(acc[6]), a7 = hadd2(acc[7]);
        float ss = hadd2(ssp);

        // reduce-scatter butterflies: group 1 (cols 0-3), group 2 (cols 4-7)
        float p0 = (l & 16) ? a2 : a0, q0 = (l & 16) ? a0 : a2;
        float p1 = (l & 16) ? a3 : a1, q1 = (l & 16) ? a1 : a3;
        p0 += __shfl_xor_sync(~0u, q0, 16);
        p1 += __shfl_xor_sync(~0u, q1, 16);
        float pp1 = (l & 8) ? p1 : p0, qq1 = (l & 8) ? p0 : p1;
        pp1 += __shfl_xor_sync(~0u, qq1, 8);
        pp1 += __shfl_xor_sync(~0u, pp1, 4);
        pp1 += __shfl_xor_sync(~0u, pp1, 2);
        pp1 += __shfl_xor_sync(~0u, pp1, 1);

        float p2 = (l & 16) ? a6 : a4, q2 = (l & 16) ? a4 : a6;
        float p3 = (l & 16) ? a7 : a5, q3 = (l & 16) ? a5 : a7;
        p2 += __shfl_xor_sync(~0u, q2, 16);
        p3 += __shfl_xor_sync(~0u, q3, 16);
        float pp2 = (l & 8) ? p3 : p2, qq2 = (l & 8) ? p2 : p3;
        pp2 += __shfl_xor_sync(~0u, qq2, 8);
        pp2 += __shfl_xor_sync(~0u, pp2, 4);
        pp2 += __shfl_xor_sync(~0u, pp2, 2);
        pp2 += __shfl_xor_sync(~0u, pp2, 1);

        // regather to lanes (only l<8 consumed)
        const int lb = l & 7;
        const float v0 = __shfl_sync(~0u, pp1, lb);
        const float v1 = __shfl_sync(~0u, pp1, 8 + lb);
        const float v2 = __shfl_sync(~0u, pp1, 16 + lb);
        const float v3 = __shfl_sync(~0u, pp1, 24 + lb);
        const float v4 = __shfl_sync(~0u, pp2, lb);
        const float v5 = __shfl_sync(~0u, pp2, 8 + lb);
        const float v6 = __shfl_sync(~0u, pp2, 16 + lb);
        const float v7 = __shfl_sync(~0u, pp2, 24 + lb);
        // full butterfly for ss (S_{t-1}; every lane needs it)
        #pragma unroll
        for (int o = 16; o; o >>= 1) ss += __shfl_xor_sync(~0u, ss, o);
        const float invS = __fdividef(1.f, ss);

        // push this warp's 8 scaled columns to all 8 CTAs (lane r -> peer r)
        if (l < 8) {
            float4 A, B;
            A.x = v0 * invS * eA.x; A.y = v1 * invS * eA.y;
            A.z = v2 * invS * eA.z; A.w = v3 * invS * eA.w;
            B.x = v4 * invS * eB.x; B.y = v5 * invS * eB.y;
            B.z = v6 * invS * eB.z; B.w = v7 * invS * eB.w;
            const unsigned daddr = rbuf + (unsigned)((sc * NS + colbase) * 4);
            const unsigned rmb = sc ? rmb1 : rmb0;
            st_async_v4(daddr,      A, rmb);
            st_async_v4(daddr + 16, B, rmb);
        }
        if (rank == 0 && tid == 0) L += __logf(ss);
        eA = eAn; eB = eBn;
        if (t >= 2) { if (sp) ph1 ^= 1; else ph0 ^= 1; }
    }

    // --- final S_{T-1} term: v_127 lives in slot 1 / mbar 1 ---
    if (w == 0) MBAR_WAIT_CLUSTER(mb1, ph1);
    __syncthreads();
    {
        const float* cur = buf[1];
        unsigned long long ssp = 0;
        #pragma unroll
        for (int k = 0; k < 4; k++) {
            ulonglong2 aa = *(const ulonglong2*)&cur[4 * l + 128 * k];
            ADD2(ssp, ssp, aa.x); ADD2(ssp, ssp, aa.y);
        }
        float ss = hadd2(ssp);
        #pragma unroll
        for (int o = 16; o; o >>= 1) ss += __shfl_xor_sync(~0u, ss, o);
        if (rank == 0 && tid == 0) {
            L += __logf(ss);
            g_L[g] = L;
            __threadfence();                     // publish g_L[g]
            unsigned old = atomicAdd(&g_done, 1u);
            if (old == NB - 1) {                 // last cluster: final reduce
                __threadfence();                 // acquire all g_L[]
                float s = 0.f;
                #pragma unroll
                for (int i = 0; i < NB; i++) s += g_L[i];
                out[0] = -s / (float)NB;
            }
        }
    }
    // align exits: no CTA leaves while a peer could still target its smem
    asm volatile("barrier.cluster.arrive.aligned;" ::: "memory");
    asm volatile("barrier.cluster.wait.aligned;"   ::: "memory");
}

// ===================== launch ====================================================
extern "C" void kernel_launch(void* const* d_in, const int* in_sizes, int n_in,
                              void* d_out, int out_size) {
    const float* em = nullptr;
    const float* tm = nullptr;
    const float* p  = nullptr;
    const int* ids  = nullptr;
    for (int i = 0; i < n_in; i++) {
        if (in_sizes[i] == NB * NT)      ids = (const int*)d_in[i];
        else if (in_sizes[i] == NS * NV) em  = (const float*)d_in[i];
        else if (in_sizes[i] == NS * NS) tm  = (const float*)d_in[i];
        else if (in_sizes[i] == NS)      p   = (const float*)d_in[i];
    }

    k_lse_part<<<4 * NS, 256>>>(em);
    k_tm_pi<<<NS + 2, 128>>>(tm, p);
    k_gather<<<NB * NT, 128>>>(em, ids);

    {
        cudaLaunchConfig_t cfg = {};
        cfg.gridDim  = dim3(NB * 8, 1, 1);
        cfg.blockDim = dim3(256, 1, 1);
        cfg.dynamicSmemBytes = 0;
        cfg.stream = 0;
        cudaLaunchAttribute attrs[1];
        attrs[0].id = cudaLaunchAttributeClusterDimension;
        attrs[0].val.clusterDim.x = 8;
        attrs[0].val.clusterDim.y = 1;
        attrs[0].val.clusterDim.z = 1;
        cfg.attrs = attrs;
        cfg.numAttrs = 1;
        cudaLaunchKernelEx(&cfg, k_forward, (float*)d_out);
    }
}